// round 14
// baseline (speedup 1.0000x reference)
#include <cuda_runtime.h>
#include <cuda_bf16.h>
#include <cstdint>

#define NROWS 262144
#define DDIM  128

typedef unsigned long long u64;
typedef unsigned int u32;

// ---------------- device scratch (no allocations allowed) ----------------
__device__ float g_e[NROWS];
__device__ float g_sp[NROWS];
__device__ float g_expw[NROWS];
__device__ float g_S_part[2048];
__device__ float g_sumeE_part[2048 * 128];
__device__ float g_seMid[128 * 128];
__device__ float g_SMid[128];
__device__ float g_S;
__device__ float g_Cvec[128];
__device__ float g_bias[128];
__device__ __align__(16) float g_Wt[128 * 256];  // Wt[k][n] fp32, k-major (proven R9 layout)
__device__ float g_gePart[4096 * 128];
__device__ float g_esumPart[4096];
__device__ float g_ge2[32 * 128];
__device__ float g_esum2[32];
__device__ float g_total;
__device__ float g_invTotal;

// ---------------- packed f32x2 helpers (FFMA2 on sm_103) ----------------
__device__ __forceinline__ u64 pack2(float x, float y) {
    u64 r;
    asm("mov.b64 %0, {%1, %2};" : "=l"(r) : "f"(x), "f"(y));
    return r;
}
__device__ __forceinline__ void fma2(u64 &d, u64 a, u64 b) {
    asm("fma.rn.f32x2 %0, %1, %2, %0;" : "+l"(d) : "l"(a), "l"(b));
}
__device__ __forceinline__ void unpack2(u64 v, float &x, float &y) {
    asm("mov.b64 {%0, %1}, %2;" : "=f"(x), "=f"(y) : "l"(v));
}
struct alignas(16) U64x2 { u64 lo, hi; };

// ---------------- smem layout for k3 (bytes) ----------------
#define ADUP_OFF  0          // 64 rows x 128 k x u64(dup) = 65536 B
#define FF_BS     65536      // 128 k x 256 n fp32 = 131072 B (k-major)
#define CVEC_OFF  196608
#define BIAS_OFF  197120
#define WVC_OFF   197632
#define ESM_OFF   198144
#define SPM_OFF   198400
#define WROW_OFF  198656
#define RED_OFF   198912     // 4*128*4 = 2048
#define SM3_BYTES 200960

// ---------------- kernel 0: build Wt[k][n] = [W1^T | W2^T] (fp32) ----------------
__global__ void k0_wt(const float* __restrict__ W1, const float* __restrict__ W2) {
    int idx = blockIdx.x * 256 + threadIdx.x;   // 0..32767
    int k = idx >> 8;
    int n = idx & 255;
    g_Wt[idx] = (n < 128) ? W1[n * 128 + k] : W2[(n - 128) * 128 + k];
}

// ---------------- kernel 1: sp, s->e, partial S, partial sum_eE (smem-staged) ----------------
#define K1_STRIDE 129
#define K1_SVW    (128 * K1_STRIDE)
#define K1_EXP    (K1_SVW + 256)
#define K1_FLOATS (K1_EXP + 128)
#define K1_BYTES  (K1_FLOATS * 4)

__global__ __launch_bounds__(128) void k1_pass1(const float* __restrict__ E,
                                                const float* __restrict__ v,
                                                const float* __restrict__ wpa,
                                                const float* __restrict__ bpa) {
    extern __shared__ float s1[];
    float*  Es  = s1;
    float2* svw = (float2*)(s1 + K1_SVW);
    float*  es  = s1 + K1_EXP;

    int t = threadIdx.x;
    int rowbase = blockIdx.x * 128;
    const float4* E4 = (const float4*)E + rowbase * 32;

    #pragma unroll
    for (int i = 0; i < 32; i++) {
        int g4 = t + i * 128;
        int r = g4 >> 5, c4 = g4 & 31;
        float4 val = E4[g4];
        Es[(c4 * 4 + 0) * K1_STRIDE + r] = val.x;
        Es[(c4 * 4 + 1) * K1_STRIDE + r] = val.y;
        Es[(c4 * 4 + 2) * K1_STRIDE + r] = val.z;
        Es[(c4 * 4 + 3) * K1_STRIDE + r] = val.w;
    }
    svw[t] = make_float2(wpa[t], v[t]);
    __syncthreads();

    float sp = 0.f, s = 0.f;
    #pragma unroll 8
    for (int k = 0; k < 128; k++) {
        float ev = Es[k * K1_STRIDE + t];
        float2 c = svw[k];
        s  = fmaf(ev, c.x, s);
        sp = fmaf(ev, c.y, sp);
    }
    s += bpa[0];
    float e = expf(s);       // softmax shift-invariant; exponents tiny
    g_sp[rowbase + t] = sp;
    g_e[rowbase + t]  = e;
    es[t] = e;
    __syncthreads();

    float acc = 0.f;
    #pragma unroll 8
    for (int r = 0; r < 128; r++) acc = fmaf(es[r], Es[t * K1_STRIDE + r], acc);
    g_sumeE_part[blockIdx.x * 128 + t] = acc;

    if (t < 32) {
        float t4 = es[t] + es[t + 32] + es[t + 64] + es[t + 96];
        #pragma unroll
        for (int off = 16; off; off >>= 1) t4 += __shfl_xor_sync(0xffffffffu, t4, off);
        if (t == 0) g_S_part[blockIdx.x] = t4;
    }
}

// ---------------- kernel 2a: parallel fold 2048 partials -> 128 ----------------
__global__ __launch_bounds__(128) void k2a_reduce() {
    int b = blockIdx.x;      // 0..127
    int d = threadIdx.x;     // 0..127
    float p = 0.f;
    #pragma unroll
    for (int j = 0; j < 16; j++) p += g_sumeE_part[(b * 16 + j) * 128 + d];
    g_seMid[b * 128 + d] = p;
    if (d == 0) {
        float s = 0.f;
        #pragma unroll
        for (int j = 0; j < 16; j++) s += g_S_part[b * 16 + j];
        g_SMid[b] = s;
    }
}

// ---------------- kernel 2b: final fold (parallel); Cvec = W2 @ sum_eE; bias; S ----------
__global__ __launch_bounds__(1024) void k2b_reduce(const float* __restrict__ W2,
                                                   const float* __restrict__ b_c1,
                                                   const float* __restrict__ b_c2) {
    __shared__ float red[1024];
    __shared__ float se[128];
    int tid = threadIdx.x;
    int d = tid & 127, h = tid >> 7;          // h = 0..7
    float p = 0.f;
    #pragma unroll
    for (int j = 0; j < 16; j++) p += g_seMid[(h * 16 + j) * 128 + d];
    red[h * 128 + d] = p;
    __syncthreads();
    if (tid < 128) {
        float s = 0.f;
        #pragma unroll
        for (int w = 0; w < 8; w++) s += red[w * 128 + tid];
        se[tid] = s;
    }
    if (tid >= 992) {    // last warp folds S in parallel with se fold
        int l = tid - 992;
        float s = g_SMid[l] + g_SMid[l + 32] + g_SMid[l + 64] + g_SMid[l + 96];
        #pragma unroll
        for (int off = 16; off; off >>= 1) s += __shfl_xor_sync(0xffffffffu, s, off);
        if (l == 0) g_S = s;
    }
    __syncthreads();
    int d2 = tid >> 3, sub = tid & 7;
    const float* wrow = W2 + d2 * 128 + sub * 16;
    const float* serow = se + sub * 16;
    float c = 0.f;
    #pragma unroll
    for (int k = 0; k < 16; k++) c = fmaf(wrow[k], serow[k], c);
    c += __shfl_xor_sync(0xffffffffu, c, 1);
    c += __shfl_xor_sync(0xffffffffu, c, 2);
    c += __shfl_xor_sync(0xffffffffu, c, 4);
    if (sub == 0) {
        g_Cvec[d2] = c;
        g_bias[d2] = b_c1[d2] + b_c2[d2];
    }
}

// ---------------- kernel 3: N-packed FFMA2 GEMM with pre-duplicated A ----------------
// 4096 blocks x 512 threads; tile 64 rows x 256 cols; K=128.
// Adup[m][k] = (a,a) as u64 in smem -> mainloop has ZERO packing MOVs:
//   per k-pair per warp: 4 LDS.128 (dup A, broadcast) + 8 LDS.64 (B) + 32 fma2.
// Warp wid owns rows wid*4..+3; lane tx owns col pairs (64*np + 2*tx, +1), np=0..3.
// Epilogue pairing: col j (np) with col j+128 (np+2) in the same thread.
__global__ __launch_bounds__(512, 1)
void k3_main(const float* __restrict__ E,
             const float* __restrict__ wvc,
             const float* __restrict__ bvcp) {
    extern __shared__ char smc[];
    u64*   Ad    = (u64*)(smc + ADUP_OFF);    // [64 m][128 k] duplicated
    float* Bs    = (float*)(smc + FF_BS);     // [128 k][256 n]
    float* cvecS = (float*)(smc + CVEC_OFF);
    float* biasS = (float*)(smc + BIAS_OFF);
    float* wvcS  = (float*)(smc + WVC_OFF);
    float* esm   = (float*)(smc + ESM_OFF);
    float* spm   = (float*)(smc + SPM_OFF);
    float* wrow  = (float*)(smc + WROW_OFF);
    float* red   = (float*)(smc + RED_OFF);

    int tid = threadIdx.x;
    int tx = tid & 31;
    int wid = tid >> 5;                 // 0..15
    int rowbase = blockIdx.x * 64;

    {   // A: 64x128 floats = 2048 float4 -> duplicate into Adup (2 STS.128 each)
        const float4* E4 = (const float4*)E + rowbase * 32;
        #pragma unroll
        for (int it = 0; it < 4; it++) {
            int g4 = tid + it * 512;
            int r = g4 >> 5, c4 = g4 & 31;
            float4 x = E4[g4];
            U64x2 lo, hi;
            lo.lo = pack2(x.x, x.x); lo.hi = pack2(x.y, x.y);
            hi.lo = pack2(x.z, x.z); hi.hi = pack2(x.w, x.w);
            U64x2* dst = (U64x2*)(Ad + r * 128 + c4 * 4);
            dst[0] = lo;
            dst[1] = hi;
        }
        // B: 128x256 = 8192 float4, linear copy
        const float4* Wt4 = (const float4*)g_Wt;
        float4* Bs4 = (float4*)Bs;
        #pragma unroll
        for (int it = 0; it < 16; it++) Bs4[tid + it * 512] = Wt4[tid + it * 512];
    }
    if (tid < 128) {
        cvecS[tid] = g_Cvec[tid];
        biasS[tid] = g_bias[tid];
        wvcS[tid]  = wvc[tid];
    }
    if (tid < 64) {
        esm[tid] = g_e[rowbase + tid];
        spm[tid] = g_sp[rowbase + tid];
    }
    float Sv  = g_S;
    float bvc = bvcp[0];
    __syncthreads();

    u64 acc[4][4];
    #pragma unroll
    for (int mm = 0; mm < 4; mm++)
        #pragma unroll
        for (int np = 0; np < 4; np++) acc[mm][np] = 0ull;

    const u64* Arow = Ad + (wid * 4) * 128;
    #pragma unroll 2
    for (int k0 = 0; k0 < 128; k0 += 2) {
        U64x2 a[4];
        #pragma unroll
        for (int mm = 0; mm < 4; mm++)
            a[mm] = *(const U64x2*)(Arow + mm * 128 + k0);   // LDS.128, lane-uniform broadcast
        const u64* b0p = (const u64*)(Bs) + (u64)k0 * 128 + tx;
        const u64* b1p = b0p + 128;
        u64 b0[4], b1[4];
        #pragma unroll
        for (int np = 0; np < 4; np++) { b0[np] = b0p[np * 32]; b1[np] = b1p[np * 32]; }
        #pragma unroll
        for (int mm = 0; mm < 4; mm++) {
            #pragma unroll
            for (int np = 0; np < 4; np++) {
                fma2(acc[mm][np], a[mm].lo, b0[np]);
                fma2(acc[mm][np], a[mm].hi, b1[np]);
            }
        }
    }

    // --- epilogue: PI + logit; pairing (j, j+128) = (np, np+2) in-thread ---
    #pragma unroll
    for (int mm = 0; mm < 4; mm++) {
        int r = wid * 4 + mm;
        float e_i = esm[r];
        float inv = 1.0f / (Sv - e_i);
        float accp = 0.f;
        #pragma unroll
        for (int np = 0; np < 2; np++) {
            float ax, ay, bx, by;
            unpack2(acc[mm][np], ax, ay);
            unpack2(acc[mm][np + 2], bx, by);
            int j = 64 * np + 2 * tx;
            float hx = ax + (cvecS[j]     - e_i * bx) * inv + biasS[j];
            float hy = ay + (cvecS[j + 1] - e_i * by) * inv + biasS[j + 1];
            accp += fmaxf(hx, 0.f) * wvcS[j] + fmaxf(hy, 0.f) * wvcS[j + 1];
        }
        #pragma unroll
        for (int off = 16; off; off >>= 1) accp += __shfl_xor_sync(0xffffffffu, accp, off);
        if (tx == 0) {
            float wv = expf(spm[r] + accp + bvc);
            wrow[r] = wv;
            g_expw[rowbase + r] = wv;
        }
    }
    __syncthreads();

    // --- block partials: ge_part[d] = sum_r w_r * E[r][d] (read lo half of Adup) ---
    {
        int d = tid & 127;
        int grp = tid >> 7;          // 0..3 -> 16 rows each
        float g = 0.f;
        #pragma unroll
        for (int rr = 0; rr < 16; rr++) {
            int r = grp * 16 + rr;
            float ev = *(const float*)((const char*)(Ad + r * 128 + d));  // lo lane = E[r][d]
            g = fmaf(wrow[r], ev, g);
        }
        red[grp * 128 + d] = g;
    }
    __syncthreads();
    if (tid < 128)
        g_gePart[blockIdx.x * 128 + tid] =
            red[tid] + red[128 + tid] + red[256 + tid] + red[384 + tid];
    if (tid < 32) {
        float s2 = wrow[tid] + wrow[tid + 32];
        #pragma unroll
        for (int off = 16; off; off >>= 1) s2 += __shfl_xor_sync(0xffffffffu, s2, off);
        if (tid == 0) g_esumPart[blockIdx.x] = s2;
    }
}

// ---------------- kernel 4a: reduce 4096 block partials -> 32 ----------------
__global__ void k4a_reduce() {
    int b0 = blockIdx.x * 128;
    int d = threadIdx.x;    // 128 threads
    float g = 0.f;
    #pragma unroll 8
    for (int j = 0; j < 128; j++) g += g_gePart[(b0 + j) * 128 + d];
    g_ge2[blockIdx.x * 128 + d] = g;
    if (d == 0) {
        float s = 0.f;
        for (int j = 0; j < 128; j++) s += g_esumPart[b0 + j];
        g_esum2[blockIdx.x] = s;
    }
}

// ---------------- kernel 4b: final ge + total (also stores 1/total) ----------------
__global__ void k4b_final(float* ge_out) {
    __shared__ float tot;
    int d = threadIdx.x;    // 128 threads
    float g = 0.f;
    #pragma unroll
    for (int c = 0; c < 32; c++) g += g_ge2[c * 128 + d];
    if (d < 32) {
        float t = g_esum2[d];
        #pragma unroll
        for (int off = 16; off; off >>= 1) t += __shfl_xor_sync(0xffffffffu, t, off);
        if (d == 0) { tot = t; g_total = t; g_invTotal = 1.0f / t; }
    }
    __syncthreads();
    if (ge_out) ge_out[d] = g / tot;
}

// ---------------- kernel 5: attention weights ----------------
__global__ void k5_attn(float* __restrict__ attn_out) {
    int i = blockIdx.x * 1024 + threadIdx.x;
    attn_out[i] = g_expw[i] * g_invTotal;
}

// ---------------- launcher ----------------
extern "C" void kernel_launch(void* const* d_in, const int* in_sizes, int n_in,
                              void* d_out, int out_size) {
    const float* E    = (const float*)d_in[0];
    const float* item = (const float*)d_in[1];
    const float* W1   = (const float*)d_in[2];
    const float* bc1  = (const float*)d_in[3];
    const float* W2   = (const float*)d_in[4];
    const float* bc2  = (const float*)d_in[5];
    const float* wpa  = (const float*)d_in[6];
    const float* bpa  = (const float*)d_in[7];
    const float* wvc  = (const float*)d_in[8];
    const float* bvc  = (const float*)d_in[9];

    float* out = (float*)d_out;
    float* ge_out = nullptr;
    float* attn_out = nullptr;
    if (out_size == NROWS + DDIM)      { ge_out = out; attn_out = out + DDIM; }
    else if (out_size == DDIM)         { ge_out = out; }
    else                               { attn_out = out; }

    cudaFuncSetAttribute(k1_pass1, cudaFuncAttributeMaxDynamicSharedMemorySize, K1_BYTES);
    cudaFuncSetAttribute(k3_main,  cudaFuncAttributeMaxDynamicSharedMemorySize, SM3_BYTES);

    k0_wt<<<128, 256>>>(W1, W2);
    k1_pass1<<<2048, 128, K1_BYTES>>>(E, item, wpa, bpa);
    k2a_reduce<<<128, 128>>>();
    k2b_reduce<<<1, 1024>>>(W2, bc1, bc2);
    k3_main<<<4096, 512, SM3_BYTES>>>(E, wvc, bvc);
    k4a_reduce<<<32, 128>>>();
    k4b_final<<<1, 128>>>(ge_out);
    if (attn_out) k5_attn<<<256, 1024>>>(attn_out);
}

// round 15
// speedup vs baseline: 2.0827x; 2.0827x over previous
#include <cuda_runtime.h>
#include <cuda_bf16.h>
#include <cstdint>

#define NROWS 262144
#define DDIM  128

typedef unsigned long long u64;
typedef unsigned int u32;

// ---------------- device scratch (no allocations allowed) ----------------
__device__ float g_e[NROWS];
__device__ float g_sp[NROWS];
__device__ float g_expw[NROWS];
__device__ float g_S_part[2048];
__device__ float g_sumeE_part[2048 * 128];
__device__ float g_seMid[128 * 128];
__device__ float g_SMid[128];
__device__ float g_S;
__device__ float g_Cvec[128];
__device__ float g_bias[128];
// Bt image: [hi | lo], each 256 rows x pitch 272B (128 bf16 cols + 16B pad) = 69632 B
__device__ __align__(16) u32 g_Bt_img[2 * 17408];
__device__ float g_gePart[2048 * 128];
__device__ float g_esumPart[2048];
__device__ float g_ge2[32 * 128];
__device__ float g_esum2[32];
__device__ float g_total;
__device__ float g_invTotal;

// ---------------- helpers ----------------
__device__ __forceinline__ u32 smem_to_u32(const void* p) {
    u32 a;
    asm("{ .reg .u64 t; cvta.to.shared.u64 t, %1; cvt.u32.u64 %0, t; }" : "=r"(a) : "l"(p));
    return a;
}
#define LDSM_X4(r, addr) \
    asm volatile("ldmatrix.sync.aligned.m8n8.x4.shared.b16 {%0,%1,%2,%3}, [%4];" \
        : "=r"((r)[0]), "=r"((r)[1]), "=r"((r)[2]), "=r"((r)[3]) : "r"(addr))

#define MMA_BF16(d, a, b0, b1) \
    asm volatile("mma.sync.aligned.m16n8k16.row.col.f32.bf16.bf16.f32 " \
        "{%0,%1,%2,%3}, {%4,%5,%6,%7}, {%8,%9}, {%0,%1,%2,%3};" \
        : "+f"((d)[0]), "+f"((d)[1]), "+f"((d)[2]), "+f"((d)[3]) \
        : "r"((a)[0]), "r"((a)[1]), "r"((a)[2]), "r"((a)[3]), "r"(b0), "r"(b1))

// ---------------- smem layout for k3 (bytes) ----------------
// A pitch: 272 B/row (128 bf16 + pad) -> conflict-free LDSM.
#define A_PITCH   272
#define A_HI_OFF  0                     // 128 * 272 = 34816
#define A_LO_OFF  34816
#define B_HI_OFF  69632                 // 256 * 272 = 69632 each
#define B_LO_OFF  139264
#define CS_OFF    69632                 // C tile aliases B region after GEMM
#define CS_PITCH  260                   // floats; 128 x 260 x 4 = 133120 B
#define CVEC_OFF  208896
#define BIAS_OFF  209408
#define WVC_OFF   209920
#define ESM_OFF   210432
#define SPM_OFF   210944
#define WROW_OFF  211456
#define RED_OFF   211968                // 16*128*4 = 8192
#define SM3_BYTES 220160

// ---------------- kernel 0b: build padded bf16 hi/lo Bt image ----------------
// Bt[n][k]: n<128 -> W1[n][k], else W2[n-128][k]; row pitch 272 B.
__global__ void k0b_bimg(const float* __restrict__ W1, const float* __restrict__ W2) {
    int idx = blockIdx.x * 256 + threadIdx.x;    // 0..16383 (bf16x2 words)
    int n = idx >> 6;
    int kp = (idx & 63) * 2;
    const float* src = (n < 128) ? (W1 + n * 128) : (W2 + (n - 128) * 128);
    float x0 = src[kp], x1 = src[kp + 1];
    __nv_bfloat16 h0 = __float2bfloat16_rn(x0);
    __nv_bfloat16 h1 = __float2bfloat16_rn(x1);
    __nv_bfloat162 hw = __nv_bfloat162(h0, h1);
    __nv_bfloat162 lw = __floats2bfloat162_rn(x0 - __bfloat162float(h0),
                                              x1 - __bfloat162float(h1));
    int off = (n * A_PITCH + kp * 2) >> 2;       // u32 index
    g_Bt_img[off]         = *(u32*)&hw;
    g_Bt_img[17408 + off] = *(u32*)&lw;
}

// ---------------- kernel 1: sp, s->e, partial S, partial sum_eE (smem-staged) ----------------
#define K1_STRIDE 129
#define K1_SVW    (128 * K1_STRIDE)
#define K1_EXP    (K1_SVW + 256)
#define K1_FLOATS (K1_EXP + 128)
#define K1_BYTES  (K1_FLOATS * 4)

__global__ __launch_bounds__(128) void k1_pass1(const float* __restrict__ E,
                                                const float* __restrict__ v,
                                                const float* __restrict__ wpa,
                                                const float* __restrict__ bpa) {
    extern __shared__ float s1[];
    float*  Es  = s1;
    float2* svw = (float2*)(s1 + K1_SVW);
    float*  es  = s1 + K1_EXP;

    int t = threadIdx.x;
    int rowbase = blockIdx.x * 128;
    const float4* E4 = (const float4*)E + rowbase * 32;

    #pragma unroll
    for (int i = 0; i < 32; i++) {
        int g4 = t + i * 128;
        int r = g4 >> 5, c4 = g4 & 31;
        float4 val = E4[g4];
        Es[(c4 * 4 + 0) * K1_STRIDE + r] = val.x;
        Es[(c4 * 4 + 1) * K1_STRIDE + r] = val.y;
        Es[(c4 * 4 + 2) * K1_STRIDE + r] = val.z;
        Es[(c4 * 4 + 3) * K1_STRIDE + r] = val.w;
    }
    svw[t] = make_float2(wpa[t], v[t]);
    __syncthreads();

    float sp = 0.f, s = 0.f;
    #pragma unroll 8
    for (int k = 0; k < 128; k++) {
        float ev = Es[k * K1_STRIDE + t];
        float2 c = svw[k];
        s  = fmaf(ev, c.x, s);
        sp = fmaf(ev, c.y, sp);
    }
    s += bpa[0];
    float e = expf(s);       // softmax shift-invariant; exponents tiny
    g_sp[rowbase + t] = sp;
    g_e[rowbase + t]  = e;
    es[t] = e;
    __syncthreads();

    float acc = 0.f;
    #pragma unroll 8
    for (int r = 0; r < 128; r++) acc = fmaf(es[r], Es[t * K1_STRIDE + r], acc);
    g_sumeE_part[blockIdx.x * 128 + t] = acc;

    if (t < 32) {
        float t4 = es[t] + es[t + 32] + es[t + 64] + es[t + 96];
        #pragma unroll
        for (int off = 16; off; off >>= 1) t4 += __shfl_xor_sync(0xffffffffu, t4, off);
        if (t == 0) g_S_part[blockIdx.x] = t4;
    }
}

// ---------------- kernel 2a: parallel fold 2048 partials -> 128 ----------------
__global__ __launch_bounds__(128) void k2a_reduce() {
    int b = blockIdx.x;      // 0..127
    int d = threadIdx.x;     // 0..127
    float p = 0.f;
    #pragma unroll
    for (int j = 0; j < 16; j++) p += g_sumeE_part[(b * 16 + j) * 128 + d];
    g_seMid[b * 128 + d] = p;
    if (d == 0) {
        float s = 0.f;
        #pragma unroll
        for (int j = 0; j < 16; j++) s += g_S_part[b * 16 + j];
        g_SMid[b] = s;
    }
}

// ---------------- kernel 2b: final fold (parallel); Cvec = W2 @ sum_eE; bias; S ----------
__global__ __launch_bounds__(1024) void k2b_reduce(const float* __restrict__ W2,
                                                   const float* __restrict__ b_c1,
                                                   const float* __restrict__ b_c2) {
    __shared__ float red[1024];
    __shared__ float se[128];
    int tid = threadIdx.x;
    int d = tid & 127, h = tid >> 7;          // h = 0..7
    float p = 0.f;
    #pragma unroll
    for (int j = 0; j < 16; j++) p += g_seMid[(h * 16 + j) * 128 + d];
    red[h * 128 + d] = p;
    __syncthreads();
    if (tid < 128) {
        float s = 0.f;
        #pragma unroll
        for (int w = 0; w < 8; w++) s += red[w * 128 + tid];
        se[tid] = s;
    }
    if (tid >= 992) {    // last warp folds S in parallel with se fold
        int l = tid - 992;
        float s = g_SMid[l] + g_SMid[l + 32] + g_SMid[l + 64] + g_SMid[l + 96];
        #pragma unroll
        for (int off = 16; off; off >>= 1) s += __shfl_xor_sync(0xffffffffu, s, off);
        if (l == 0) g_S = s;
    }
    __syncthreads();
    int d2 = tid >> 3, sub = tid & 7;
    const float* wrow = W2 + d2 * 128 + sub * 16;
    const float* serow = se + sub * 16;
    float c = 0.f;
    #pragma unroll
    for (int k = 0; k < 16; k++) c = fmaf(wrow[k], serow[k], c);
    c += __shfl_xor_sync(0xffffffffu, c, 1);
    c += __shfl_xor_sync(0xffffffffu, c, 2);
    c += __shfl_xor_sync(0xffffffffu, c, 4);
    if (sub == 0) {
        g_Cvec[d2] = c;
        g_bias[d2] = b_c1[d2] + b_c2[d2];
    }
}

// ---------------- kernel 3: HMMA (mma.sync bf16 3-split) GEMM + PI + logits + partials ----
// 2048 blocks x 512 threads; tile 128 rows x 256 cols; K=128.
// Warp wid: m-block (wid&7)*16, n-half (wid>>3)*128. 384 HMMA/warp.
__global__ __launch_bounds__(512, 1)
void k3_main(const float* __restrict__ E,
             const float* __restrict__ wvc,
             const float* __restrict__ bvcp) {
    extern __shared__ char smc[];
    float* Cs    = (float*)(smc + CS_OFF);
    float* cvecS = (float*)(smc + CVEC_OFF);
    float* biasS = (float*)(smc + BIAS_OFF);
    float* wvcS  = (float*)(smc + WVC_OFF);
    float* esm   = (float*)(smc + ESM_OFF);
    float* spm   = (float*)(smc + SPM_OFF);
    float* wrow  = (float*)(smc + WROW_OFF);
    float* red   = (float*)(smc + RED_OFF);

    int tid = threadIdx.x;
    int lane = tid & 31;
    int wid = tid >> 5;             // 0..15
    int rowbase = blockIdx.x * 128;
    u32 smem_base = smem_to_u32(smc);

    // --- copy Bt images (hi|lo contiguous): 8704 float4 ---
    {
        const float4* bsrc = (const float4*)g_Bt_img;
        float4* bdst = (float4*)(smc + B_HI_OFF);
        #pragma unroll
        for (int i = 0; i < 17; i++) bdst[tid + i * 512] = bsrc[tid + i * 512];
    }
    // --- load E tile, split bf16 hi/lo, store padded (pitch 272B) ---
    {
        const float4* E4 = (const float4*)E + rowbase * 32;
        #pragma unroll
        for (int i = 0; i < 8; i++) {
            int g4 = tid + i * 512;
            int r = g4 >> 5;
            int off = r * A_PITCH + (g4 & 31) * 8;
            float4 x = E4[g4];
            __nv_bfloat16 h0 = __float2bfloat16_rn(x.x);
            __nv_bfloat16 h1 = __float2bfloat16_rn(x.y);
            __nv_bfloat16 h2 = __float2bfloat16_rn(x.z);
            __nv_bfloat16 h3 = __float2bfloat16_rn(x.w);
            __nv_bfloat162 hw0 = __nv_bfloat162(h0, h1);
            __nv_bfloat162 hw1 = __nv_bfloat162(h2, h3);
            __nv_bfloat162 lw0 = __floats2bfloat162_rn(x.x - __bfloat162float(h0),
                                                       x.y - __bfloat162float(h1));
            __nv_bfloat162 lw1 = __floats2bfloat162_rn(x.z - __bfloat162float(h2),
                                                       x.w - __bfloat162float(h3));
            u64 hp = (u64)(*(u32*)&hw0) | ((u64)(*(u32*)&hw1) << 32);
            u64 lp = (u64)(*(u32*)&lw0) | ((u64)(*(u32*)&lw1) << 32);
            *(u64*)(smc + A_HI_OFF + off) = hp;
            *(u64*)(smc + A_LO_OFF + off) = lp;
        }
    }
    if (tid < 128) {
        cvecS[tid] = g_Cvec[tid];
        biasS[tid] = g_bias[tid];
        wvcS[tid]  = wvc[tid];
        esm[tid]   = g_e[rowbase + tid];
        spm[tid]   = g_sp[rowbase + tid];
    }
    float Sv  = g_S;
    float bvc = bvcp[0];
    __syncthreads();

    // --- HMMA mainloop ---
    int m0 = (wid & 7) * 16;
    int n0 = (wid >> 3) * 128;

    u32 aAddrH = smem_base + A_HI_OFF
               + (u32)(m0 + (lane & 7) + ((lane >> 3) & 1) * 8) * A_PITCH
               + ((lane >> 4) & 1) * 16;
    u32 aAddrL = aAddrH + (A_LO_OFF - A_HI_OFF);
    u32 bAddrH = smem_base + B_HI_OFF
               + (u32)(n0 + (lane & 7) + ((lane >> 4) & 1) * 8) * A_PITCH
               + ((lane >> 3) & 1) * 16;
    u32 bAddrL = bAddrH + (B_LO_OFF - B_HI_OFF);

    float d[16][4];
    #pragma unroll
    for (int i = 0; i < 16; i++)
        #pragma unroll
        for (int j = 0; j < 4; j++) d[i][j] = 0.f;

    #pragma unroll
    for (int ks = 0; ks < 8; ks++) {
        u32 ah[4], al[4];
        LDSM_X4(ah, aAddrH + ks * 32);
        LDSM_X4(al, aAddrL + ks * 32);
        #pragma unroll
        for (int nb = 0; nb < 8; nb++) {
            u32 bo = nb * (16 * A_PITCH) + ks * 32;
            u32 bh[4], bl[4];
            LDSM_X4(bh, bAddrH + bo);
            MMA_BF16(d[2 * nb],     ah, bh[0], bh[1]);
            MMA_BF16(d[2 * nb + 1], ah, bh[2], bh[3]);
            MMA_BF16(d[2 * nb],     al, bh[0], bh[1]);
            MMA_BF16(d[2 * nb + 1], al, bh[2], bh[3]);
            LDSM_X4(bl, bAddrL + bo);
            MMA_BF16(d[2 * nb],     ah, bl[0], bl[1]);
            MMA_BF16(d[2 * nb + 1], ah, bl[2], bl[3]);
        }
    }
    __syncthreads();   // everyone done reading B before C overwrites it

    // --- store C tile (fragment layout: rows m0+(lane>>2), +8; cols (lane&3)*2) ---
    {
        int r0 = m0 + (lane >> 2);
        int c0 = n0 + (lane & 3) * 2;
        #pragma unroll
        for (int nb8 = 0; nb8 < 16; nb8++) {
            *(float2*)(Cs + r0 * CS_PITCH + c0 + nb8 * 8)       = make_float2(d[nb8][0], d[nb8][1]);
            *(float2*)(Cs + (r0 + 8) * CS_PITCH + c0 + nb8 * 8) = make_float2(d[nb8][2], d[nb8][3]);
        }
    }
    __syncthreads();

    // --- epilogue: 4 threads per row ---
    {
        int r = tid >> 2, q = tid & 3;
        float e_i = esm[r];
        float inv = 1.0f / (Sv - e_i);
        const float* Crow = Cs + r * CS_PITCH;
        float pi = 0.f;
        #pragma unroll 8
        for (int jj = 0; jj < 32; jj++) {
            int j = jj * 4 + q;
            float a  = Crow[j];
            float bb = Crow[j + 128];
            float hv = a + (cvecS[j] - e_i * bb) * inv + biasS[j];
            pi += fmaxf(hv, 0.f) * wvcS[j];
        }
        pi += __shfl_xor_sync(0xffffffffu, pi, 1);
        pi += __shfl_xor_sync(0xffffffffu, pi, 2);
        if (q == 0) {
            float wv = expf(spm[r] + pi + bvc);
            wrow[r] = wv;
            g_expw[rowbase + r] = wv;
        }
    }
    __syncthreads();

    // --- block partials: ge_part[d] = sum_r w_r * E[r][d] (E = hi+lo from smem) ---
    {
        float a0 = 0.f, a1 = 0.f, a2 = 0.f, a3 = 0.f;
        #pragma unroll
        for (int rr = 0; rr < 8; rr++) {
            int r = wid * 8 + rr;
            float wv = wrow[r];
            int base = r * A_PITCH + lane * 4;
            float2 h0 = __bfloat1622float2(*(const __nv_bfloat162*)(smc + A_HI_OFF + base));
            float2 l0 = __bfloat1622float2(*(const __nv_bfloat162*)(smc + A_LO_OFF + base));
            float2 h1 = __bfloat1622float2(*(const __nv_bfloat162*)(smc + A_HI_OFF + base + 128));
            float2 l1 = __bfloat1622float2(*(const __nv_bfloat162*)(smc + A_LO_OFF + base + 128));
            a0 = fmaf(wv, h0.x + l0.x, a0);
            a1 = fmaf(wv, h0.y + l0.y, a1);
            a2 = fmaf(wv, h1.x + l1.x, a2);
            a3 = fmaf(wv, h1.y + l1.y, a3);
        }
        float2* r2 = (float2*)red;
        r2[wid * 64 + lane]      = make_float2(a0, a1);   // cols 2l, 2l+1
        r2[wid * 64 + 32 + lane] = make_float2(a2, a3);   // cols 64+2l, 65+2l
    }
    __syncthreads();
    if (tid < 128) {
        float g = 0.f;
        #pragma unroll
        for (int w = 0; w < 16; w++) g += red[w * 128 + tid];
        g_gePart[blockIdx.x * 128 + tid] = g;
    }
    if (tid < 32) {
        float s2 = wrow[tid] + wrow[tid + 32] + wrow[tid + 64] + wrow[tid + 96];
        #pragma unroll
        for (int off = 16; off; off >>= 1) s2 += __shfl_xor_sync(0xffffffffu, s2, off);
        if (tid == 0) g_esumPart[blockIdx.x] = s2;
    }
}

// ---------------- kernel 4a: reduce 2048 block partials -> 32 ----------------
__global__ void k4a_reduce() {
    int b0 = blockIdx.x * 64;
    int d = threadIdx.x;    // 128 threads
    float g = 0.f;
    #pragma unroll 8
    for (int j = 0; j < 64; j++) g += g_gePart[(b0 + j) * 128 + d];
    g_ge2[blockIdx.x * 128 + d] = g;
    if (d == 0) {
        float s = 0.f;
        for (int j = 0; j < 64; j++) s += g_esumPart[b0 + j];
        g_esum2[blockIdx.x] = s;
    }
}

// ---------------- kernel 4b: final ge + total (also stores 1/total) ----------------
__global__ void k4b_final(float* ge_out) {
    __shared__ float tot;
    int d = threadIdx.x;    // 128 threads
    float g = 0.f;
    #pragma unroll
    for (int c = 0; c < 32; c++) g += g_ge2[c * 128 + d];
    if (d < 32) {
        float t = g_esum2[d];
        #pragma unroll
        for (int off = 16; off; off >>= 1) t += __shfl_xor_sync(0xffffffffu, t, off);
        if (d == 0) { tot = t; g_total = t; g_invTotal = 1.0f / t; }
    }
    __syncthreads();
    if (ge_out) ge_out[d] = g / tot;
}

// ---------------- kernel 5: attention weights ----------------
__global__ void k5_attn(float* __restrict__ attn_out) {
    int i = blockIdx.x * 1024 + threadIdx.x;
    attn_out[i] = g_expw[i] * g_invTotal;
}

// ---------------- launcher ----------------
extern "C" void kernel_launch(void* const* d_in, const int* in_sizes, int n_in,
                              void* d_out, int out_size) {
    const float* E    = (const float*)d_in[0];
    const float* item = (const float*)d_in[1];
    const float* W1   = (const float*)d_in[2];
    const float* bc1  = (const float*)d_in[3];
    const float* W2   = (const float*)d_in[4];
    const float* bc2  = (const float*)d_in[5];
    const float* wpa  = (const float*)d_in[6];
    const float* bpa  = (const float*)d_in[7];
    const float* wvc  = (const float*)d_in[8];
    const float* bvc  = (const float*)d_in[9];

    float* out = (float*)d_out;
    float* ge_out = nullptr;
    float* attn_out = nullptr;
    if (out_size == NROWS + DDIM)      { ge_out = out; attn_out = out + DDIM; }
    else if (out_size == DDIM)         { ge_out = out; }
    else                               { attn_out = out; }

    cudaFuncSetAttribute(k1_pass1, cudaFuncAttributeMaxDynamicSharedMemorySize, K1_BYTES);
    cudaFuncSetAttribute(k3_main,  cudaFuncAttributeMaxDynamicSharedMemorySize, SM3_BYTES);

    k0b_bimg<<<64, 256>>>(W1, W2);
    k1_pass1<<<2048, 128, K1_BYTES>>>(E, item, wpa, bpa);
    k2a_reduce<<<128, 128>>>();
    k2b_reduce<<<1, 1024>>>(W2, bc1, bc2);
    k3_main<<<2048, 512, SM3_BYTES>>>(E, wvc, bvc);
    k4a_reduce<<<32, 128>>>();
    k4b_final<<<1, 128>>>(ge_out);
    if (attn_out) k5_attn<<<256, 1024>>>(attn_out);
}

// round 16
// speedup vs baseline: 2.2938x; 1.1013x over previous
#include <cuda_runtime.h>
#include <cuda_bf16.h>
#include <cstdint>

#define NROWS 262144
#define DDIM  128

typedef unsigned long long u64;
typedef unsigned int u32;

// ---------------- device scratch (no allocations allowed) ----------------
__device__ float g_e[NROWS];
__device__ float g_sp[NROWS];
__device__ float g_expw[NROWS];
__device__ float g_S_part[2048];
__device__ float g_sumeE_part[2048 * 128];
__device__ float g_seMid[128 * 128];
__device__ float g_SMid[128];
__device__ float g_S;
__device__ float g_Cvec[128];
__device__ float g_bias[128];
// Bt image: [hi | lo], each 256 rows x pitch 272B (128 bf16 cols + 16B pad) = 69632 B
__device__ __align__(16) u32 g_Bt_img[2 * 17408];
__device__ float g_gePart[2048 * 128];
__device__ float g_esumPart[2048];
__device__ float g_ge2[32 * 128];
__device__ float g_esum2[32];
__device__ float g_total;
__device__ float g_invTotal;

// ---------------- helpers ----------------
__device__ __forceinline__ u32 smem_to_u32(const void* p) {
    u32 a;
    asm("{ .reg .u64 t; cvta.to.shared.u64 t, %1; cvt.u32.u64 %0, t; }" : "=r"(a) : "l"(p));
    return a;
}
#define LDSM_X4(r, addr) \
    asm volatile("ldmatrix.sync.aligned.m8n8.x4.shared.b16 {%0,%1,%2,%3}, [%4];" \
        : "=r"((r)[0]), "=r"((r)[1]), "=r"((r)[2]), "=r"((r)[3]) : "r"(addr))

#define MMA_BF16(d, a, b0, b1) \
    asm volatile("mma.sync.aligned.m16n8k16.row.col.f32.bf16.bf16.f32 " \
        "{%0,%1,%2,%3}, {%4,%5,%6,%7}, {%8,%9}, {%0,%1,%2,%3};" \
        : "+f"((d)[0]), "+f"((d)[1]), "+f"((d)[2]), "+f"((d)[3]) \
        : "r"((a)[0]), "r"((a)[1]), "r"((a)[2]), "r"((a)[3]), "r"(b0), "r"(b1))

// ---------------- smem layout for k3 (bytes) ----------------
// A pitch: 272 B/row (128 bf16 + pad) -> conflict-free LDSM.
#define A_PITCH   272
#define A_HI_OFF  0                     // 128 * 272 = 34816
#define A_LO_OFF  34816
#define B_HI_OFF  69632                 // 256 * 272 = 69632 each
#define B_LO_OFF  139264
#define CVEC_OFF  208896
#define BIAS_OFF  209408
#define WVC_OFF   209920
#define ESM_OFF   210432
#define SPM_OFF   210944
#define WROW_OFF  211456
#define RED_OFF   211968                // 16*128*4 = 8192 (piQ reuses the first 1KB)
#define SM3_BYTES 220160

// ---------------- kernel 0b: build padded bf16 hi/lo Bt image ----------------
// Bt[n][k]: n<128 -> W1[n][k], else W2[n-128][k]; row pitch 272 B.
__global__ void k0b_bimg(const float* __restrict__ W1, const float* __restrict__ W2) {
    int idx = blockIdx.x * 256 + threadIdx.x;    // 0..16383 (bf16x2 words)
    int n = idx >> 6;
    int kp = (idx & 63) * 2;
    const float* src = (n < 128) ? (W1 + n * 128) : (W2 + (n - 128) * 128);
    float x0 = src[kp], x1 = src[kp + 1];
    __nv_bfloat16 h0 = __float2bfloat16_rn(x0);
    __nv_bfloat16 h1 = __float2bfloat16_rn(x1);
    __nv_bfloat162 hw = __nv_bfloat162(h0, h1);
    __nv_bfloat162 lw = __floats2bfloat162_rn(x0 - __bfloat162float(h0),
                                              x1 - __bfloat162float(h1));
    int off = (n * A_PITCH + kp * 2) >> 2;       // u32 index
    g_Bt_img[off]         = *(u32*)&hw;
    g_Bt_img[17408 + off] = *(u32*)&lw;
}

// ---------------- kernel 1: sp, s->e, partial S, partial sum_eE (smem-staged) ----------------
#define K1_STRIDE 129
#define K1_SVW    (128 * K1_STRIDE)
#define K1_EXP    (K1_SVW + 256)
#define K1_FLOATS (K1_EXP + 128)
#define K1_BYTES  (K1_FLOATS * 4)

__global__ __launch_bounds__(128) void k1_pass1(const float* __restrict__ E,
                                                const float* __restrict__ v,
                                                const float* __restrict__ wpa,
                                                const float* __restrict__ bpa) {
    extern __shared__ float s1[];
    float*  Es  = s1;
    float2* svw = (float2*)(s1 + K1_SVW);
    float*  es  = s1 + K1_EXP;

    int t = threadIdx.x;
    int rowbase = blockIdx.x * 128;
    const float4* E4 = (const float4*)E + rowbase * 32;

    #pragma unroll
    for (int i = 0; i < 32; i++) {
        int g4 = t + i * 128;
        int r = g4 >> 5, c4 = g4 & 31;
        float4 val = E4[g4];
        Es[(c4 * 4 + 0) * K1_STRIDE + r] = val.x;
        Es[(c4 * 4 + 1) * K1_STRIDE + r] = val.y;
        Es[(c4 * 4 + 2) * K1_STRIDE + r] = val.z;
        Es[(c4 * 4 + 3) * K1_STRIDE + r] = val.w;
    }
    svw[t] = make_float2(wpa[t], v[t]);
    __syncthreads();

    float sp = 0.f, s = 0.f;
    #pragma unroll 8
    for (int k = 0; k < 128; k++) {
        float ev = Es[k * K1_STRIDE + t];
        float2 c = svw[k];
        s  = fmaf(ev, c.x, s);
        sp = fmaf(ev, c.y, sp);
    }
    s += bpa[0];
    float e = expf(s);       // softmax shift-invariant; exponents tiny
    g_sp[rowbase + t] = sp;
    g_e[rowbase + t]  = e;
    es[t] = e;
    __syncthreads();

    float acc = 0.f;
    #pragma unroll 8
    for (int r = 0; r < 128; r++) acc = fmaf(es[r], Es[t * K1_STRIDE + r], acc);
    g_sumeE_part[blockIdx.x * 128 + t] = acc;

    if (t < 32) {
        float t4 = es[t] + es[t + 32] + es[t + 64] + es[t + 96];
        #pragma unroll
        for (int off = 16; off; off >>= 1) t4 += __shfl_xor_sync(0xffffffffu, t4, off);
        if (t == 0) g_S_part[blockIdx.x] = t4;
    }
}

// ---------------- kernel 2a: parallel fold 2048 partials -> 128 ----------------
__global__ __launch_bounds__(128) void k2a_reduce() {
    int b = blockIdx.x;      // 0..127
    int d = threadIdx.x;     // 0..127
    float p = 0.f;
    #pragma unroll
    for (int j = 0; j < 16; j++) p += g_sumeE_part[(b * 16 + j) * 128 + d];
    g_seMid[b * 128 + d] = p;
    if (d == 0) {
        float s = 0.f;
        #pragma unroll
        for (int j = 0; j < 16; j++) s += g_S_part[b * 16 + j];
        g_SMid[b] = s;
    }
}

// ---------------- kernel 2b: final fold (parallel); Cvec = W2 @ sum_eE; bias; S ----------
__global__ __launch_bounds__(1024) void k2b_reduce(const float* __restrict__ W2,
                                                   const float* __restrict__ b_c1,
                                                   const float* __restrict__ b_c2) {
    __shared__ float red[1024];
    __shared__ float se[128];
    int tid = threadIdx.x;
    int d = tid & 127, h = tid >> 7;          // h = 0..7
    float p = 0.f;
    #pragma unroll
    for (int j = 0; j < 16; j++) p += g_seMid[(h * 16 + j) * 128 + d];
    red[h * 128 + d] = p;
    __syncthreads();
    if (tid < 128) {
        float s = 0.f;
        #pragma unroll
        for (int w = 0; w < 8; w++) s += red[w * 128 + tid];
        se[tid] = s;
    }
    if (tid >= 992) {    // last warp folds S in parallel with se fold
        int l = tid - 992;
        float s = g_SMid[l] + g_SMid[l + 32] + g_SMid[l + 64] + g_SMid[l + 96];
        #pragma unroll
        for (int off = 16; off; off >>= 1) s += __shfl_xor_sync(0xffffffffu, s, off);
        if (l == 0) g_S = s;
    }
    __syncthreads();
    int d2 = tid >> 3, sub = tid & 7;
    const float* wrow = W2 + d2 * 128 + sub * 16;
    const float* serow = se + sub * 16;
    float c = 0.f;
    #pragma unroll
    for (int k = 0; k < 16; k++) c = fmaf(wrow[k], serow[k], c);
    c += __shfl_xor_sync(0xffffffffu, c, 1);
    c += __shfl_xor_sync(0xffffffffu, c, 2);
    c += __shfl_xor_sync(0xffffffffu, c, 4);
    if (sub == 0) {
        g_Cvec[d2] = c;
        g_bias[d2] = b_c1[d2] + b_c2[d2];
    }
}

// ---------------- kernel 3: HMMA bf16 3-split GEMM, register epilogue ----------------
// 2048 blocks x 512 threads; tile 128 rows x 256 cols; K=128.
// Warp wid: m-block m0=(wid&7)*16, n-quarter q=wid>>3.
// Warp covers cols {q*64 + [0,64)} U {128 + q*64 + [0,64)} -> paired (j, j+128)
// live in the SAME thread's d regs: d[i] (i<8) pairs with d[i+8].
// MMA order: per nb-group of 4, term-by-term (ah*bh x8, al*bh x8, ah*bl x8) ->
// same-d reuse distance 8 (was 2): accumulator chains hidden.
__global__ __launch_bounds__(512, 1)
void k3_main(const float* __restrict__ E,
             const float* __restrict__ wvc,
             const float* __restrict__ bvcp) {
    extern __shared__ char smc[];
    float* cvecS = (float*)(smc + CVEC_OFF);
    float* biasS = (float*)(smc + BIAS_OFF);
    float* wvcS  = (float*)(smc + WVC_OFF);
    float* esm   = (float*)(smc + ESM_OFF);
    float* spm   = (float*)(smc + SPM_OFF);
    float* wrow  = (float*)(smc + WROW_OFF);
    float* red   = (float*)(smc + RED_OFF);
    float* piQ   = red;                 // [2][128], reused before partials

    int tid = threadIdx.x;
    int lane = tid & 31;
    int wid = tid >> 5;             // 0..15
    int rowbase = blockIdx.x * 128;
    u32 smem_base = smem_to_u32(smc);

    // --- copy Bt images (hi|lo contiguous): 8704 float4 ---
    {
        const float4* bsrc = (const float4*)g_Bt_img;
        float4* bdst = (float4*)(smc + B_HI_OFF);
        #pragma unroll
        for (int i = 0; i < 17; i++) bdst[tid + i * 512] = bsrc[tid + i * 512];
    }
    // --- load E tile, split bf16 hi/lo, store padded (pitch 272B) ---
    {
        const float4* E4 = (const float4*)E + rowbase * 32;
        #pragma unroll
        for (int i = 0; i < 8; i++) {
            int g4 = tid + i * 512;
            int r = g4 >> 5;
            int off = r * A_PITCH + (g4 & 31) * 8;
            float4 x = E4[g4];
            __nv_bfloat16 h0 = __float2bfloat16_rn(x.x);
            __nv_bfloat16 h1 = __float2bfloat16_rn(x.y);
            __nv_bfloat16 h2 = __float2bfloat16_rn(x.z);
            __nv_bfloat16 h3 = __float2bfloat16_rn(x.w);
            __nv_bfloat162 hw0 = __nv_bfloat162(h0, h1);
            __nv_bfloat162 hw1 = __nv_bfloat162(h2, h3);
            __nv_bfloat162 lw0 = __floats2bfloat162_rn(x.x - __bfloat162float(h0),
                                                       x.y - __bfloat162float(h1));
            __nv_bfloat162 lw1 = __floats2bfloat162_rn(x.z - __bfloat162float(h2),
                                                       x.w - __bfloat162float(h3));
            u64 hp = (u64)(*(u32*)&hw0) | ((u64)(*(u32*)&hw1) << 32);
            u64 lp = (u64)(*(u32*)&lw0) | ((u64)(*(u32*)&lw1) << 32);
            *(u64*)(smc + A_HI_OFF + off) = hp;
            *(u64*)(smc + A_LO_OFF + off) = lp;
        }
    }
    if (tid < 128) {
        cvecS[tid] = g_Cvec[tid];
        biasS[tid] = g_bias[tid];
        wvcS[tid]  = wvc[tid];
        esm[tid]   = g_e[rowbase + tid];
        spm[tid]   = g_sp[rowbase + tid];
    }
    float Sv  = g_S;
    float bvc = bvcp[0];
    __syncthreads();

    // --- HMMA mainloop ---
    int m0 = (wid & 7) * 16;
    int q  = wid >> 3;               // n-quarter
    int n0 = q * 64;

    u32 aAddrH = smem_base + A_HI_OFF
               + (u32)(m0 + (lane & 7) + ((lane >> 3) & 1) * 8) * A_PITCH
               + ((lane >> 4) & 1) * 16;
    u32 aAddrL = aAddrH + (A_LO_OFF - A_HI_OFF);
    u32 bAddrH = smem_base + B_HI_OFF
               + (u32)(n0 + (lane & 7) + ((lane >> 4) & 1) * 8) * A_PITCH
               + ((lane >> 3) & 1) * 16;
    u32 bAddrL = bAddrH + (B_LO_OFF - B_HI_OFF);

    float d[16][4];
    #pragma unroll
    for (int i = 0; i < 16; i++)
        #pragma unroll
        for (int j = 0; j < 4; j++) d[i][j] = 0.f;

    #pragma unroll
    for (int ks = 0; ks < 8; ks++) {
        u32 ah[4], al[4];
        LDSM_X4(ah, aAddrH + ks * 32);
        LDSM_X4(al, aAddrL + ks * 32);
        #pragma unroll
        for (int g = 0; g < 2; g++) {      // g=0: cols n0+[0,64); g=1: +128
            u32 bh[4][4];
            #pragma unroll
            for (int t = 0; t < 4; t++)
                LDSM_X4(bh[t], bAddrH + t * (16 * A_PITCH) + g * (128 * A_PITCH) + ks * 32);
            #pragma unroll
            for (int t = 0; t < 4; t++) {
                int s = g * 8 + 2 * t;
                MMA_BF16(d[s],     ah, bh[t][0], bh[t][1]);
                MMA_BF16(d[s + 1], ah, bh[t][2], bh[t][3]);
            }
            #pragma unroll
            for (int t = 0; t < 4; t++) {
                int s = g * 8 + 2 * t;
                MMA_BF16(d[s],     al, bh[t][0], bh[t][1]);
                MMA_BF16(d[s + 1], al, bh[t][2], bh[t][3]);
            }
            u32 bl[4][4];
            #pragma unroll
            for (int t = 0; t < 4; t++)
                LDSM_X4(bl[t], bAddrL + t * (16 * A_PITCH) + g * (128 * A_PITCH) + ks * 32);
            #pragma unroll
            for (int t = 0; t < 4; t++) {
                int s = g * 8 + 2 * t;
                MMA_BF16(d[s],     ah, bl[t][0], bl[t][1]);
                MMA_BF16(d[s + 1], ah, bl[t][2], bl[t][3]);
            }
        }
    }

    // --- register epilogue: (j, j+128) in-thread; pi partials per n-quarter ---
    {
        int r0 = m0 + (lane >> 2);
        float e0 = esm[r0],     inv0 = 1.0f / (Sv - e0);
        float e1 = esm[r0 + 8], inv1 = 1.0f / (Sv - e1);
        float pi0 = 0.f, pi1 = 0.f;
        #pragma unroll
        for (int i = 0; i < 8; i++) {
            int j = q * 64 + (i >> 1) * 16 + (i & 1) * 8 + (lane & 3) * 2;
            float cv0 = cvecS[j], cv1 = cvecS[j + 1];
            float bi0 = biasS[j], bi1 = biasS[j + 1];
            float wv0 = wvcS[j],  wv1 = wvcS[j + 1];
            float h00 = d[i][0] + (cv0 - e0 * d[i + 8][0]) * inv0 + bi0;
            float h01 = d[i][1] + (cv1 - e0 * d[i + 8][1]) * inv0 + bi1;
            float h10 = d[i][2] + (cv0 - e1 * d[i + 8][2]) * inv1 + bi0;
            float h11 = d[i][3] + (cv1 - e1 * d[i + 8][3]) * inv1 + bi1;
            pi0 += fmaxf(h00, 0.f) * wv0 + fmaxf(h01, 0.f) * wv1;
            pi1 += fmaxf(h10, 0.f) * wv0 + fmaxf(h11, 0.f) * wv1;
        }
        pi0 += __shfl_xor_sync(0xffffffffu, pi0, 1);
        pi0 += __shfl_xor_sync(0xffffffffu, pi0, 2);
        pi1 += __shfl_xor_sync(0xffffffffu, pi1, 1);
        pi1 += __shfl_xor_sync(0xffffffffu, pi1, 2);
        if ((lane & 3) == 0) {
            piQ[q * 128 + r0]     = pi0;
            piQ[q * 128 + r0 + 8] = pi1;
        }
    }
    __syncthreads();
    if (tid < 128) {
        float pi = piQ[tid] + piQ[128 + tid];
        float wv = expf(spm[tid] + pi + bvc);
        wrow[tid] = wv;
        g_expw[rowbase + tid] = wv;
    }
    __syncthreads();

    // --- block partials: ge_part[d] = sum_r w_r * E[r][d] (E = hi+lo from smem) ---
    {
        float a0 = 0.f, a1 = 0.f, a2 = 0.f, a3 = 0.f;
        #pragma unroll
        for (int rr = 0; rr < 8; rr++) {
            int r = wid * 8 + rr;
            float wv = wrow[r];
            int base = r * A_PITCH + lane * 4;
            float2 h0 = __bfloat1622float2(*(const __nv_bfloat162*)(smc + A_HI_OFF + base));
            float2 l0 = __bfloat1622float2(*(const __nv_bfloat162*)(smc + A_LO_OFF + base));
            float2 h1 = __bfloat1622float2(*(const __nv_bfloat162*)(smc + A_HI_OFF + base + 128));
            float2 l1 = __bfloat1622float2(*(const __nv_bfloat162*)(smc + A_LO_OFF + base + 128));
            a0 = fmaf(wv, h0.x + l0.x, a0);
            a1 = fmaf(wv, h0.y + l0.y, a1);
            a2 = fmaf(wv, h1.x + l1.x, a2);
            a3 = fmaf(wv, h1.y + l1.y, a3);
        }
        float2* r2 = (float2*)red;
        r2[wid * 64 + lane]      = make_float2(a0, a1);   // cols 2l, 2l+1
        r2[wid * 64 + 32 + lane] = make_float2(a2, a3);   // cols 64+2l, 65+2l
    }
    __syncthreads();
    if (tid < 128) {
        float g = 0.f;
        #pragma unroll
        for (int w = 0; w < 16; w++) g += red[w * 128 + tid];
        g_gePart[blockIdx.x * 128 + tid] = g;
    }
    if (tid < 32) {
        float s2 = wrow[tid] + wrow[tid + 32] + wrow[tid + 64] + wrow[tid + 96];
        #pragma unroll
        for (int off = 16; off; off >>= 1) s2 += __shfl_xor_sync(0xffffffffu, s2, off);
        if (tid == 0) g_esumPart[blockIdx.x] = s2;
    }
}

// ---------------- kernel 4a: reduce 2048 block partials -> 32 ----------------
__global__ void k4a_reduce() {
    int b0 = blockIdx.x * 64;
    int d = threadIdx.x;    // 128 threads
    float g = 0.f;
    #pragma unroll 8
    for (int j = 0; j < 64; j++) g += g_gePart[(b0 + j) * 128 + d];
    g_ge2[blockIdx.x * 128 + d] = g;
    if (d == 0) {
        float s = 0.f;
        for (int j = 0; j < 64; j++) s += g_esumPart[b0 + j];
        g_esum2[blockIdx.x] = s;
    }
}

// ---------------- kernel 4b: final ge + total (also stores 1/total) ----------------
__global__ void k4b_final(float* ge_out) {
    __shared__ float tot;
    int d = threadIdx.x;    // 128 threads
    float g = 0.f;
    #pragma unroll
    for (int c = 0; c < 32; c++) g += g_ge2[c * 128 + d];
    if (d < 32) {
        float t = g_esum2[d];
        #pragma unroll
        for (int off = 16; off; off >>= 1) t += __shfl_xor_sync(0xffffffffu, t, off);
        if (d == 0) { tot = t; g_total = t; g_invTotal = 1.0f / t; }
    }
    __syncthreads();
    if (ge_out) ge_out[d] = g / tot;
}

// ---------------- kernel 5: attention weights ----------------
__global__ void k5_attn(float* __restrict__ attn_out) {
    int i = blockIdx.x * 1024 + threadIdx.x;
    attn_out[i] = g_expw[i] * g_invTotal;
}

// ---------------- launcher ----------------
extern "C" void kernel_launch(void* const* d_in, const int* in_sizes, int n_in,
                              void* d_out, int out_size) {
    const float* E    = (const float*)d_in[0];
    const float* item = (const float*)d_in[1];
    const float* W1   = (const float*)d_in[2];
    const float* bc1  = (const float*)d_in[3];
    const float* W2   = (const float*)d_in[4];
    const float* bc2  = (const float*)d_in[5];
    const float* wpa  = (const float*)d_in[6];
    const float* bpa  = (const float*)d_in[7];
    const float* wvc  = (const float*)d_in[8];
    const float* bvc  = (const float*)d_in[9];

    float* out = (float*)d_out;
    float* ge_out = nullptr;
    float* attn_out = nullptr;
    if (out_size == NROWS + DDIM)      { ge_out = out; attn_out = out + DDIM; }
    else if (out_size == DDIM)         { ge_out = out; }
    else                               { attn_out = out; }

    cudaFuncSetAttribute(k1_pass1, cudaFuncAttributeMaxDynamicSharedMemorySize, K1_BYTES);
    cudaFuncSetAttribute(k3_main,  cudaFuncAttributeMaxDynamicSharedMemorySize, SM3_BYTES);

    k0b_bimg<<<64, 256>>>(W1, W2);
    k1_pass1<<<2048, 128, K1_BYTES>>>(E, item, wpa, bpa);
    k2a_reduce<<<128, 128>>>();
    k2b_reduce<<<1, 1024>>>(W2, bc1, bc2);
    k3_main<<<2048, 512, SM3_BYTES>>>(E, wvc, bvc);
    k4a_reduce<<<32, 128>>>();
    k4b_final<<<1, 128>>>(ge_out);
    if (attn_out) k5_attn<<<256, 1024>>>(attn_out);
}

// round 17
// speedup vs baseline: 2.6477x; 1.1543x over previous
#include <cuda_runtime.h>
#include <cuda_bf16.h>
#include <cstdint>

#define NROWS 262144
#define DDIM  128
#define NTILES 2048
#define K3_GRID 148

typedef unsigned long long u64;
typedef unsigned int u32;

// ---------------- device scratch (no allocations allowed) ----------------
__device__ float g_e[NROWS];
__device__ float g_sp[NROWS];
__device__ float g_expw[NROWS];
__device__ float g_S_part[2048];
__device__ float g_sumeE_part[2048 * 128];
__device__ float g_seMid[128 * 128];
__device__ float g_SMid[128];
__device__ float g_S;
__device__ float g_Cvec[128];
__device__ float g_bias[128];
// Bt image: [hi | lo], each 256 rows x pitch 272B (128 bf16 cols + 16B pad) = 69632 B
__device__ __align__(16) u32 g_Bt_img[2 * 17408];
__device__ float g_gePart[2048 * 128];
__device__ float g_esumPart[2048];
__device__ float g_ge2[32 * 128];
__device__ float g_esum2[32];
__device__ float g_total;
__device__ float g_invTotal;

// ---------------- helpers ----------------
__device__ __forceinline__ u32 smem_to_u32(const void* p) {
    u32 a;
    asm("{ .reg .u64 t; cvta.to.shared.u64 t, %1; cvt.u32.u64 %0, t; }" : "=r"(a) : "l"(p));
    return a;
}
#define LDSM_X4(r, addr) \
    asm volatile("ldmatrix.sync.aligned.m8n8.x4.shared.b16 {%0,%1,%2,%3}, [%4];" \
        : "=r"((r)[0]), "=r"((r)[1]), "=r"((r)[2]), "=r"((r)[3]) : "r"(addr))

#define MMA_BF16(d, a, b0, b1) \
    asm volatile("mma.sync.aligned.m16n8k16.row.col.f32.bf16.bf16.f32 " \
        "{%0,%1,%2,%3}, {%4,%5,%6,%7}, {%8,%9}, {%0,%1,%2,%3};" \
        : "+f"((d)[0]), "+f"((d)[1]), "+f"((d)[2]), "+f"((d)[3]) \
        : "r"((a)[0]), "r"((a)[1]), "r"((a)[2]), "r"((a)[3]), "r"(b0), "r"(b1))

// ---------------- smem layout for k3 (bytes) ----------------
#define A_PITCH   272
#define A_HI_OFF  0                     // 128 * 272 = 34816
#define A_LO_OFF  34816
#define B_HI_OFF  69632                 // 256 * 272 = 69632 each
#define B_LO_OFF  139264
#define CVEC_OFF  208896
#define BIAS_OFF  209408
#define WVC_OFF   209920
#define ESM_OFF   210432
#define SPM_OFF   210944
#define WROW_OFF  211456
#define RED_OFF   211968                // 16*128*4 = 8192 (piQ reuses the first 1KB)
#define SM3_BYTES 220160

// ---------------- kernel 0b: build padded bf16 hi/lo Bt image ----------------
__global__ void k0b_bimg(const float* __restrict__ W1, const float* __restrict__ W2) {
    int idx = blockIdx.x * 256 + threadIdx.x;    // 0..16383 (bf16x2 words)
    int n = idx >> 6;
    int kp = (idx & 63) * 2;
    const float* src = (n < 128) ? (W1 + n * 128) : (W2 + (n - 128) * 128);
    float x0 = src[kp], x1 = src[kp + 1];
    __nv_bfloat16 h0 = __float2bfloat16_rn(x0);
    __nv_bfloat16 h1 = __float2bfloat16_rn(x1);
    __nv_bfloat162 hw = __nv_bfloat162(h0, h1);
    __nv_bfloat162 lw = __floats2bfloat162_rn(x0 - __bfloat162float(h0),
                                              x1 - __bfloat162float(h1));
    int off = (n * A_PITCH + kp * 2) >> 2;       // u32 index
    g_Bt_img[off]         = *(u32*)&hw;
    g_Bt_img[17408 + off] = *(u32*)&lw;
}

// ---------------- kernel 1: sp, s->e, partial S, partial sum_eE (smem-staged) ----------------
#define K1_STRIDE 129
#define K1_SVW    (128 * K1_STRIDE)
#define K1_EXP    (K1_SVW + 256)
#define K1_FLOATS (K1_EXP + 128)
#define K1_BYTES  (K1_FLOATS * 4)

__global__ __launch_bounds__(128) void k1_pass1(const float* __restrict__ E,
                                                const float* __restrict__ v,
                                                const float* __restrict__ wpa,
                                                const float* __restrict__ bpa) {
    extern __shared__ float s1[];
    float*  Es  = s1;
    float2* svw = (float2*)(s1 + K1_SVW);
    float*  es  = s1 + K1_EXP;

    int t = threadIdx.x;
    int rowbase = blockIdx.x * 128;
    const float4* E4 = (const float4*)E + rowbase * 32;

    #pragma unroll
    for (int i = 0; i < 32; i++) {
        int g4 = t + i * 128;
        int r = g4 >> 5, c4 = g4 & 31;
        float4 val = E4[g4];
        Es[(c4 * 4 + 0) * K1_STRIDE + r] = val.x;
        Es[(c4 * 4 + 1) * K1_STRIDE + r] = val.y;
        Es[(c4 * 4 + 2) * K1_STRIDE + r] = val.z;
        Es[(c4 * 4 + 3) * K1_STRIDE + r] = val.w;
    }
    svw[t] = make_float2(wpa[t], v[t]);
    __syncthreads();

    float sp = 0.f, s = 0.f;
    #pragma unroll 8
    for (int k = 0; k < 128; k++) {
        float ev = Es[k * K1_STRIDE + t];
        float2 c = svw[k];
        s  = fmaf(ev, c.x, s);
        sp = fmaf(ev, c.y, sp);
    }
    s += bpa[0];
    float e = expf(s);       // softmax shift-invariant; exponents tiny
    g_sp[rowbase + t] = sp;
    g_e[rowbase + t]  = e;
    es[t] = e;
    __syncthreads();

    float acc = 0.f;
    #pragma unroll 8
    for (int r = 0; r < 128; r++) acc = fmaf(es[r], Es[t * K1_STRIDE + r], acc);
    g_sumeE_part[blockIdx.x * 128 + t] = acc;

    if (t < 32) {
        float t4 = es[t] + es[t + 32] + es[t + 64] + es[t + 96];
        #pragma unroll
        for (int off = 16; off; off >>= 1) t4 += __shfl_xor_sync(0xffffffffu, t4, off);
        if (t == 0) g_S_part[blockIdx.x] = t4;
    }
}

// ---------------- kernel 2a: parallel fold 2048 partials -> 128 ----------------
__global__ __launch_bounds__(128) void k2a_reduce() {
    int b = blockIdx.x;      // 0..127
    int d = threadIdx.x;     // 0..127
    float p = 0.f;
    #pragma unroll
    for (int j = 0; j < 16; j++) p += g_sumeE_part[(b * 16 + j) * 128 + d];
    g_seMid[b * 128 + d] = p;
    if (d == 0) {
        float s = 0.f;
        #pragma unroll
        for (int j = 0; j < 16; j++) s += g_S_part[b * 16 + j];
        g_SMid[b] = s;
    }
}

// ---------------- kernel 2b: final fold (parallel); Cvec = W2 @ sum_eE; bias; S ----------
__global__ __launch_bounds__(1024) void k2b_reduce(const float* __restrict__ W2,
                                                   const float* __restrict__ b_c1,
                                                   const float* __restrict__ b_c2) {
    __shared__ float red[1024];
    __shared__ float se[128];
    int tid = threadIdx.x;
    int d = tid & 127, h = tid >> 7;          // h = 0..7
    float p = 0.f;
    #pragma unroll
    for (int j = 0; j < 16; j++) p += g_seMid[(h * 16 + j) * 128 + d];
    red[h * 128 + d] = p;
    __syncthreads();
    if (tid < 128) {
        float s = 0.f;
        #pragma unroll
        for (int w = 0; w < 8; w++) s += red[w * 128 + tid];
        se[tid] = s;
    }
    if (tid >= 992) {    // last warp folds S in parallel with se fold
        int l = tid - 992;
        float s = g_SMid[l] + g_SMid[l + 32] + g_SMid[l + 64] + g_SMid[l + 96];
        #pragma unroll
        for (int off = 16; off; off >>= 1) s += __shfl_xor_sync(0xffffffffu, s, off);
        if (l == 0) g_S = s;
    }
    __syncthreads();
    int d2 = tid >> 3, sub = tid & 7;
    const float* wrow = W2 + d2 * 128 + sub * 16;
    const float* serow = se + sub * 16;
    float c = 0.f;
    #pragma unroll
    for (int k = 0; k < 16; k++) c = fmaf(wrow[k], serow[k], c);
    c += __shfl_xor_sync(0xffffffffu, c, 1);
    c += __shfl_xor_sync(0xffffffffu, c, 2);
    c += __shfl_xor_sync(0xffffffffu, c, 4);
    if (sub == 0) {
        g_Cvec[d2] = c;
        g_bias[d2] = b_c1[d2] + b_c2[d2];
    }
}

// ---------------- kernel 3: PERSISTENT HMMA bf16 3-split GEMM ----------------
// 148 blocks x 512 threads; each block loads B ONCE, loops over tiles
// (tile = bid, bid+148, ...), 13-14 tiles each. Tile = 128 rows x 256 cols, K=128.
// Mainloop/epilogue identical to R16 (register epilogue, n-quarter layout).
__global__ __launch_bounds__(512, 1)
void k3_main(const float* __restrict__ E,
             const float* __restrict__ wvc,
             const float* __restrict__ bvcp) {
    extern __shared__ char smc[];
    float* cvecS = (float*)(smc + CVEC_OFF);
    float* biasS = (float*)(smc + BIAS_OFF);
    float* wvcS  = (float*)(smc + WVC_OFF);
    float* esm   = (float*)(smc + ESM_OFF);
    float* spm   = (float*)(smc + SPM_OFF);
    float* wrow  = (float*)(smc + WROW_OFF);
    float* red   = (float*)(smc + RED_OFF);
    float* piQ   = red;                 // [2][128], reused before partials

    int tid = threadIdx.x;
    int lane = tid & 31;
    int wid = tid >> 5;             // 0..15
    u32 smem_base = smem_to_u32(smc);

    // --- one-time: copy Bt images (hi|lo contiguous): 8704 float4 ---
    {
        const float4* bsrc = (const float4*)g_Bt_img;
        float4* bdst = (float4*)(smc + B_HI_OFF);
        #pragma unroll
        for (int i = 0; i < 17; i++) bdst[tid + i * 512] = bsrc[tid + i * 512];
    }
    if (tid < 128) {
        cvecS[tid] = g_Cvec[tid];
        biasS[tid] = g_bias[tid];
        wvcS[tid]  = wvc[tid];
    }
    float Sv  = g_S;
    float bvc = bvcp[0];

    // --- per-warp constants for the mainloop ---
    int m0 = (wid & 7) * 16;
    int q  = wid >> 3;               // n-quarter
    int n0 = q * 64;
    u32 aAddrH = smem_base + A_HI_OFF
               + (u32)(m0 + (lane & 7) + ((lane >> 3) & 1) * 8) * A_PITCH
               + ((lane >> 4) & 1) * 16;
    u32 aAddrL = aAddrH + (A_LO_OFF - A_HI_OFF);
    u32 bAddrH = smem_base + B_HI_OFF
               + (u32)(n0 + (lane & 7) + ((lane >> 4) & 1) * 8) * A_PITCH
               + ((lane >> 3) & 1) * 16;
    u32 bAddrL = bAddrH + (B_LO_OFF - B_HI_OFF);

    // --- persistent tile loop ---
    for (int tile = blockIdx.x; tile < NTILES; tile += K3_GRID) {
        int rowbase = tile * 128;

        // fill A (convert to bf16 hi/lo, padded pitch) + per-tile row scalars
        {
            const float4* E4 = (const float4*)E + rowbase * 32;
            #pragma unroll
            for (int i = 0; i < 8; i++) {
                int g4 = tid + i * 512;
                int r = g4 >> 5;
                int off = r * A_PITCH + (g4 & 31) * 8;
                float4 x = E4[g4];
                __nv_bfloat16 h0 = __float2bfloat16_rn(x.x);
                __nv_bfloat16 h1 = __float2bfloat16_rn(x.y);
                __nv_bfloat16 h2 = __float2bfloat16_rn(x.z);
                __nv_bfloat16 h3 = __float2bfloat16_rn(x.w);
                __nv_bfloat162 hw0 = __nv_bfloat162(h0, h1);
                __nv_bfloat162 hw1 = __nv_bfloat162(h2, h3);
                __nv_bfloat162 lw0 = __floats2bfloat162_rn(x.x - __bfloat162float(h0),
                                                           x.y - __bfloat162float(h1));
                __nv_bfloat162 lw1 = __floats2bfloat162_rn(x.z - __bfloat162float(h2),
                                                           x.w - __bfloat162float(h3));
                u64 hp = (u64)(*(u32*)&hw0) | ((u64)(*(u32*)&hw1) << 32);
                u64 lp = (u64)(*(u32*)&lw0) | ((u64)(*(u32*)&lw1) << 32);
                *(u64*)(smc + A_HI_OFF + off) = hp;
                *(u64*)(smc + A_LO_OFF + off) = lp;
            }
            if (tid < 128) {
                esm[tid] = g_e[rowbase + tid];
                spm[tid] = g_sp[rowbase + tid];
            }
        }
        __syncthreads();

        // --- HMMA mainloop (term-by-term reorder, reuse distance 8) ---
        float d[16][4];
        #pragma unroll
        for (int i = 0; i < 16; i++)
            #pragma unroll
            for (int j = 0; j < 4; j++) d[i][j] = 0.f;

        #pragma unroll
        for (int ks = 0; ks < 8; ks++) {
            u32 ah[4], al[4];
            LDSM_X4(ah, aAddrH + ks * 32);
            LDSM_X4(al, aAddrL + ks * 32);
            #pragma unroll
            for (int g = 0; g < 2; g++) {      // g=0: cols n0+[0,64); g=1: +128
                u32 bh[4][4];
                #pragma unroll
                for (int t = 0; t < 4; t++)
                    LDSM_X4(bh[t], bAddrH + t * (16 * A_PITCH) + g * (128 * A_PITCH) + ks * 32);
                #pragma unroll
                for (int t = 0; t < 4; t++) {
                    int s = g * 8 + 2 * t;
                    MMA_BF16(d[s],     ah, bh[t][0], bh[t][1]);
                    MMA_BF16(d[s + 1], ah, bh[t][2], bh[t][3]);
                }
                #pragma unroll
                for (int t = 0; t < 4; t++) {
                    int s = g * 8 + 2 * t;
                    MMA_BF16(d[s],     al, bh[t][0], bh[t][1]);
                    MMA_BF16(d[s + 1], al, bh[t][2], bh[t][3]);
                }
                u32 bl[4][4];
                #pragma unroll
                for (int t = 0; t < 4; t++)
                    LDSM_X4(bl[t], bAddrL + t * (16 * A_PITCH) + g * (128 * A_PITCH) + ks * 32);
                #pragma unroll
                for (int t = 0; t < 4; t++) {
                    int s = g * 8 + 2 * t;
                    MMA_BF16(d[s],     ah, bl[t][0], bl[t][1]);
                    MMA_BF16(d[s + 1], ah, bl[t][2], bl[t][3]);
                }
            }
        }

        // --- register epilogue: (j, j+128) in-thread; pi partials per n-quarter ---
        {
            int r0 = m0 + (lane >> 2);
            float e0 = esm[r0],     inv0 = 1.0f / (Sv - e0);
            float e1 = esm[r0 + 8], inv1 = 1.0f / (Sv - e1);
            float pi0 = 0.f, pi1 = 0.f;
            #pragma unroll
            for (int i = 0; i < 8; i++) {
                int j = q * 64 + (i >> 1) * 16 + (i & 1) * 8 + (lane & 3) * 2;
                float cv0 = cvecS[j], cv1 = cvecS[j + 1];
                float bi0 = biasS[j], bi1 = biasS[j + 1];
                float wv0 = wvcS[j],  wv1 = wvcS[j + 1];
                float h00 = d[i][0] + (cv0 - e0 * d[i + 8][0]) * inv0 + bi0;
                float h01 = d[i][1] + (cv1 - e0 * d[i + 8][1]) * inv0 + bi1;
                float h10 = d[i][2] + (cv0 - e1 * d[i + 8][2]) * inv1 + bi0;
                float h11 = d[i][3] + (cv1 - e1 * d[i + 8][3]) * inv1 + bi1;
                pi0 += fmaxf(h00, 0.f) * wv0 + fmaxf(h01, 0.f) * wv1;
                pi1 += fmaxf(h10, 0.f) * wv0 + fmaxf(h11, 0.f) * wv1;
            }
            pi0 += __shfl_xor_sync(0xffffffffu, pi0, 1);
            pi0 += __shfl_xor_sync(0xffffffffu, pi0, 2);
            pi1 += __shfl_xor_sync(0xffffffffu, pi1, 1);
            pi1 += __shfl_xor_sync(0xffffffffu, pi1, 2);
            if ((lane & 3) == 0) {
                piQ[q * 128 + r0]     = pi0;
                piQ[q * 128 + r0 + 8] = pi1;
            }
        }
        __syncthreads();
        if (tid < 128) {
            float pi = piQ[tid] + piQ[128 + tid];
            float wv = expf(spm[tid] + pi + bvc);
            wrow[tid] = wv;
            g_expw[rowbase + tid] = wv;
        }
        __syncthreads();

        // --- block partials: ge_part[d] = sum_r w_r * E[r][d] (E = hi+lo from smem) ---
        {
            float a0 = 0.f, a1 = 0.f, a2 = 0.f, a3 = 0.f;
            #pragma unroll
            for (int rr = 0; rr < 8; rr++) {
                int r = wid * 8 + rr;
                float wv = wrow[r];
                int base = r * A_PITCH + lane * 4;
                float2 h0 = __bfloat1622float2(*(const __nv_bfloat162*)(smc + A_HI_OFF + base));
                float2 l0 = __bfloat1622float2(*(const __nv_bfloat162*)(smc + A_LO_OFF + base));
                float2 h1 = __bfloat1622float2(*(const __nv_bfloat162*)(smc + A_HI_OFF + base + 128));
                float2 l1 = __bfloat1622float2(*(const __nv_bfloat162*)(smc + A_LO_OFF + base + 128));
                a0 = fmaf(wv, h0.x + l0.x, a0);
                a1 = fmaf(wv, h0.y + l0.y, a1);
                a2 = fmaf(wv, h1.x + l1.x, a2);
                a3 = fmaf(wv, h1.y + l1.y, a3);
            }
            float2* r2 = (float2*)red;
            r2[wid * 64 + lane]      = make_float2(a0, a1);   // cols 2l, 2l+1
            r2[wid * 64 + 32 + lane] = make_float2(a2, a3);   // cols 64+2l, 65+2l
        }
        __syncthreads();
        if (tid < 128) {
            float g = 0.f;
            #pragma unroll
            for (int w = 0; w < 16; w++) g += red[w * 128 + tid];
            g_gePart[tile * 128 + tid] = g;
        }
        if (tid < 32) {
            float s2 = wrow[tid] + wrow[tid + 32] + wrow[tid + 64] + wrow[tid + 96];
            #pragma unroll
            for (int off = 16; off; off >>= 1) s2 += __shfl_xor_sync(0xffffffffu, s2, off);
            if (tid == 0) g_esumPart[tile] = s2;
        }
        __syncthreads();   // A, red free before next tile's fill
    }
}

// ---------------- kernel 4a: reduce 2048 block partials -> 32 ----------------
__global__ void k4a_reduce() {
    int b0 = blockIdx.x * 64;
    int d = threadIdx.x;    // 128 threads
    float g = 0.f;
    #pragma unroll 8
    for (int j = 0; j < 64; j++) g += g_gePart[(b0 + j) * 128 + d];
    g_ge2[blockIdx.x * 128 + d] = g;
    if (d == 0) {
        float s = 0.f;
        for (int j = 0; j < 64; j++) s += g_esumPart[b0 + j];
        g_esum2[blockIdx.x] = s;
    }
}

// ---------------- kernel 4b: final ge + total (also stores 1/total) ----------------
__global__ void k4b_final(float* ge_out) {
    __shared__ float tot;
    int d = threadIdx.x;    // 128 threads
    float g = 0.f;
    #pragma unroll
    for (int c = 0; c < 32; c++) g += g_ge2[c * 128 + d];
    if (d < 32) {
        float t = g_esum2[d];
        #pragma unroll
        for (int off = 16; off; off >>= 1) t += __shfl_xor_sync(0xffffffffu, t, off);
        if (d == 0) { tot = t; g_total = t; g_invTotal = 1.0f / t; }
    }
    __syncthreads();
    if (ge_out) ge_out[d] = g / tot;
}

// ---------------- kernel 5: attention weights ----------------
__global__ void k5_attn(float* __restrict__ attn_out) {
    int i = blockIdx.x * 1024 + threadIdx.x;
    attn_out[i] = g_expw[i] * g_invTotal;
}

// ---------------- launcher ----------------
extern "C" void kernel_launch(void* const* d_in, const int* in_sizes, int n_in,
                              void* d_out, int out_size) {
    const float* E    = (const float*)d_in[0];
    const float* item = (const float*)d_in[1];
    const float* W1   = (const float*)d_in[2];
    const float* bc1  = (const float*)d_in[3];
    const float* W2   = (const float*)d_in[4];
    const float* bc2  = (const float*)d_in[5];
    const float* wpa  = (const float*)d_in[6];
    const float* bpa  = (const float*)d_in[7];
    const float* wvc  = (const float*)d_in[8];
    const float* bvc  = (const float*)d_in[9];

    float* out = (float*)d_out;
    float* ge_out = nullptr;
    float* attn_out = nullptr;
    if (out_size == NROWS + DDIM)      { ge_out = out; attn_out = out + DDIM; }
    else if (out_size == DDIM)         { ge_out = out; }
    else                               { attn_out = out; }

    cudaFuncSetAttribute(k1_pass1, cudaFuncAttributeMaxDynamicSharedMemorySize, K1_BYTES);
    cudaFuncSetAttribute(k3_main,  cudaFuncAttributeMaxDynamicSharedMemorySize, SM3_BYTES);

    k0b_bimg<<<64, 256>>>(W1, W2);
    k1_pass1<<<2048, 128, K1_BYTES>>>(E, item, wpa, bpa);
    k2a_reduce<<<128, 128>>>();
    k2b_reduce<<<1, 1024>>>(W2, bc1, bc2);
    k3_main<<<K3_GRID, 512, SM3_BYTES>>>(E, wvc, bvc);
    k4a_reduce<<<32, 128>>>();
    k4b_final<<<1, 128>>>(ge_out);
    if (attn_out) k5_attn<<<256, 1024>>>(attn_out);
}